// round 1
// baseline (speedup 1.0000x reference)
#include <cuda_runtime.h>
#include <math.h>

// ---------------------------------------------------------------------------
// DTree forward: h = relu(x W_pre^T + b_pre); cosine routing over 127 nodes;
// per-leaf path probabilities -> s_w; entropy -> global scalar scale;
// out[b,o] = scale * sum_l s_w[b,l] * (h[b,:] . W_leaf[l*256+o,:] + b_leaf[l*256+o])
//
// Strategy: fuse the 275-GFLOP leaf contraction into ONE tiled GEMM with
// K = 128 leaves x 514 (513 features + bias-as-column). s_w folded into the
// A-tile on shared-memory store. fp32 with packed fma.rn.f32x2 inner loop.
// ---------------------------------------------------------------------------

#define BATCH   8192
#define DIN     512
#define D1      513
#define HS      528      // padded h row stride: col 513 = 1.0 (bias), 514..527 = 0
#define NODES   127
#define LEAVES  128
#define DOUT    256

typedef unsigned long long u64;

// -------------------- scratch (device globals; no allocation) --------------
__device__ __align__(16) float g_h[BATCH * HS];        // 17.3 MB, relu'd h (padded)
__device__ float g_swt[LEAVES * BATCH];                // s_w transposed [l][b]
__device__ float g_right[BATCH * 128];                 // cosine logits (col 127 unused)
__device__ float g_invh[BATCH];
__device__ float g_invw[NODES];
__device__ float g_entpart[1024];
__device__ float g_scale;

// -------------------- helpers ----------------------------------------------
__device__ __forceinline__ u64 pk2(float x) {
    u64 r;
    asm("mov.b64 %0, {%1, %1};" : "=l"(r) : "f"(x));
    return r;
}

// ============================================================================
// k0: pad g_h bias/zero columns; compute right_w row inverse norms
// ============================================================================
__global__ void k0_init(const float* __restrict__ right_w) {
    int gid = blockIdx.x * 256 + threadIdx.x;
    if (gid < BATCH) {
        g_h[gid * HS + 513] = 1.0f;
        #pragma unroll
        for (int c = 514; c < HS; c++) g_h[gid * HS + c] = 0.0f;
    }
    if (blockIdx.x == 0 && threadIdx.x < NODES) {
        int n = threadIdx.x;
        float s = 0.0f;
        #pragma unroll 4
        for (int d = 0; d < D1; d++) {
            float v = right_w[n * D1 + d];
            s += v * v;
        }
        g_invw[n] = 1.0f / fmaxf(sqrtf(s), 1e-12f);
    }
}

// ============================================================================
// k1: h = relu(x @ W_pre^T + b_pre)  -> g_h[:, 0:513]
// M=8192, N=513, K=512.  128x128x16 tile, 256 thr, 8x8 per thread (scalar fp32)
// ============================================================================
__global__ __launch_bounds__(256) void k1_pre(const float* __restrict__ x,
                                              const float* __restrict__ Wp,
                                              const float* __restrict__ bp) {
    __shared__ __align__(16) float As[16][129];
    __shared__ __align__(16) float Bs[16][129];
    int m0 = blockIdx.y * 128, n0 = blockIdx.x * 128;
    int tid = threadIdx.x, ty = tid / 16, tx = tid % 16;
    int ar = tid >> 1, aq = (tid & 1) * 8;

    float acc[8][8];
    #pragma unroll
    for (int i = 0; i < 8; i++)
        #pragma unroll
        for (int j = 0; j < 8; j++) acc[i][j] = 0.0f;

    for (int kt = 0; kt < 32; kt++) {
        int kk = kt * 16;
        float4 v0 = *(const float4*)(x + (m0 + ar) * DIN + kk + aq);
        float4 v1 = *(const float4*)(x + (m0 + ar) * DIN + kk + aq + 4);
        int n = n0 + ar;
        float4 w0 = make_float4(0.f, 0.f, 0.f, 0.f), w1 = w0;
        if (n < D1) {
            w0 = *(const float4*)(Wp + n * DIN + kk + aq);
            w1 = *(const float4*)(Wp + n * DIN + kk + aq + 4);
        }
        __syncthreads();
        As[aq + 0][ar] = v0.x; As[aq + 1][ar] = v0.y; As[aq + 2][ar] = v0.z; As[aq + 3][ar] = v0.w;
        As[aq + 4][ar] = v1.x; As[aq + 5][ar] = v1.y; As[aq + 6][ar] = v1.z; As[aq + 7][ar] = v1.w;
        Bs[aq + 0][ar] = w0.x; Bs[aq + 1][ar] = w0.y; Bs[aq + 2][ar] = w0.z; Bs[aq + 3][ar] = w0.w;
        Bs[aq + 4][ar] = w1.x; Bs[aq + 5][ar] = w1.y; Bs[aq + 6][ar] = w1.z; Bs[aq + 7][ar] = w1.w;
        __syncthreads();
        #pragma unroll
        for (int k = 0; k < 16; k++) {
            float a[8], b[8];
            #pragma unroll
            for (int i = 0; i < 8; i++) a[i] = As[k][ty + 16 * i];
            #pragma unroll
            for (int j = 0; j < 8; j++) b[j] = Bs[k][tx + 16 * j];
            #pragma unroll
            for (int i = 0; i < 8; i++)
                #pragma unroll
                for (int j = 0; j < 8; j++) acc[i][j] += a[i] * b[j];
        }
    }
    #pragma unroll
    for (int j = 0; j < 8; j++) {
        int n = n0 + tx + 16 * j;
        if (n >= D1) continue;
        float bias = bp[n];
        #pragma unroll
        for (int i = 0; i < 8; i++) {
            int b = m0 + ty + 16 * i;
            g_h[b * HS + n] = fmaxf(acc[i][j] + bias, 0.0f);
        }
    }
}

// ============================================================================
// k2: per-row inverse L2 norm of h (cols 0..512 only)
// ============================================================================
__global__ void k2_invh() {
    int w = threadIdx.x / 32, lane = threadIdx.x % 32;
    int b = blockIdx.x * 8 + w;
    const float* row = g_h + b * HS;
    float s = 0.0f;
    for (int d = lane; d < D1; d += 32) {
        float v = row[d];
        s += v * v;
    }
    #pragma unroll
    for (int o = 16; o > 0; o >>= 1) s += __shfl_xor_sync(0xffffffffu, s, o);
    if (lane == 0) g_invh[b] = 1.0f / fmaxf(sqrtf(s), 1e-12f);
}

// ============================================================================
// k3: right[b,n] = invh[b]*invw[n] * (h[b,:513] . right_w[n,:513])
// M=8192, N=127 (one tile), K=513 -> 33 k-tiles of 16
// ============================================================================
__global__ __launch_bounds__(256) void k3_right(const float* __restrict__ rw) {
    __shared__ __align__(16) float As[16][129];
    __shared__ __align__(16) float Bs[16][129];
    int m0 = blockIdx.y * 128;
    int tid = threadIdx.x, ty = tid / 16, tx = tid % 16;
    int ar = tid >> 1, aq = (tid & 1) * 8;

    float acc[8][8];
    #pragma unroll
    for (int i = 0; i < 8; i++)
        #pragma unroll
        for (int j = 0; j < 8; j++) acc[i][j] = 0.0f;

    for (int kt = 0; kt < 33; kt++) {
        int kk = kt * 16;
        float4 v0 = *(const float4*)(g_h + (m0 + ar) * HS + kk + aq);
        float4 v1 = *(const float4*)(g_h + (m0 + ar) * HS + kk + aq + 4);
        int n = ar;
        float bv[8];
        #pragma unroll
        for (int q = 0; q < 8; q++) {
            int d = kk + aq + q;
            bv[q] = (n < NODES && d < D1) ? rw[n * D1 + d] : 0.0f;
        }
        __syncthreads();
        As[aq + 0][ar] = v0.x; As[aq + 1][ar] = v0.y; As[aq + 2][ar] = v0.z; As[aq + 3][ar] = v0.w;
        As[aq + 4][ar] = v1.x; As[aq + 5][ar] = v1.y; As[aq + 6][ar] = v1.z; As[aq + 7][ar] = v1.w;
        #pragma unroll
        for (int q = 0; q < 8; q++) Bs[aq + q][ar] = bv[q];
        __syncthreads();
        #pragma unroll
        for (int k = 0; k < 16; k++) {
            float a[8], b[8];
            #pragma unroll
            for (int i = 0; i < 8; i++) a[i] = As[k][ty + 16 * i];
            #pragma unroll
            for (int j = 0; j < 8; j++) b[j] = Bs[k][tx + 16 * j];
            #pragma unroll
            for (int i = 0; i < 8; i++)
                #pragma unroll
                for (int j = 0; j < 8; j++) acc[i][j] += a[i] * b[j];
        }
    }
    #pragma unroll
    for (int i = 0; i < 8; i++) {
        int b = m0 + ty + 16 * i;
        float ih = g_invh[b];
        #pragma unroll
        for (int j = 0; j < 8; j++) {
            int n = tx + 16 * j;
            if (n < NODES) g_right[b * 128 + n] = acc[i][j] * ih * g_invw[n];
        }
    }
}

// ============================================================================
// k4: routing. One warp per sample: node log-probs in smem, 7-step path sums,
// s_w (transposed store), per-block entropy partial (deterministic).
// ============================================================================
__global__ __launch_bounds__(256) void k4_route(const int* __restrict__ ridx,
                                                const int* __restrict__ rside) {
    __shared__ int s_idx[LEAVES * 7];
    __shared__ int s_side[LEAVES * 7];
    __shared__ float s_lr[8][128];   // log clip right_dist
    __shared__ float s_ll[8][128];   // log clip left_dist
    __shared__ float s_ent[8];

    int tid = threadIdx.x;
    for (int t = tid; t < LEAVES * 7; t += 256) {
        s_idx[t] = ridx[t];
        s_side[t] = rside[t];
    }
    __syncthreads();

    int w = tid / 32, lane = tid % 32;
    int b = blockIdx.x * 8 + w;

    for (int n = lane; n < NODES; n += 32) {
        float r = g_right[b * 128 + n];
        float rd = 0.5f * (1.0f - r);
        float ld = 0.5f * (1.0f + r);
        s_lr[w][n] = logf(fminf(fmaxf(rd, 0.01f), 0.99f));
        s_ll[w][n] = logf(fminf(fmaxf(ld, 0.01f), 0.99f));
    }
    __syncwarp();

    float ent = 0.0f;
    for (int li = lane; li < LEAVES; li += 32) {
        float lp = 0.0f;
        #pragma unroll
        for (int j = 0; j < 7; j++) {
            int node = s_idx[li * 7 + j];
            int side = s_side[li * 7 + j];
            lp += side ? s_ll[w][node] : s_lr[w][node];
        }
        float s = expf(lp);
        g_swt[li * BATCH + b] = s;
        ent -= s * lp;
    }
    #pragma unroll
    for (int o = 16; o > 0; o >>= 1) ent += __shfl_xor_sync(0xffffffffu, ent, o);
    if (lane == 0) s_ent[w] = ent;
    __syncthreads();
    if (tid == 0) {
        float t = 0.0f;
        #pragma unroll
        for (int i = 0; i < 8; i++) t += s_ent[i];
        g_entpart[blockIdx.x] = t;
    }
}

// ============================================================================
// k5: deterministic entropy reduction -> scale scalar
// ============================================================================
__global__ void k5_scale() {
    __shared__ float sm[256];
    float s = 0.0f;
    for (int i = threadIdx.x; i < 1024; i += 256) s += g_entpart[i];
    sm[threadIdx.x] = s;
    __syncthreads();
    for (int st = 128; st > 0; st >>= 1) {
        if (threadIdx.x < st) sm[threadIdx.x] += sm[threadIdx.x + st];
        __syncthreads();
    }
    if (threadIdx.x == 0) {
        float max_ent = (128.0f / 6.0f) * logf(6.0f);
        g_scale = 1.0f + (sm[0] / (float)BATCH) / max_ent;
    }
}

// ============================================================================
// k6: fused leaf contraction.
// out[b,o] = scale * sum_l s_w[b,l] * (h[b,:] . Wl[l*256+o,:] + bl[l*256+o])
// Single GEMM, K = 128 leaves x 528 (513 real + bias col 513 + zero pad).
// 128x128 block tile, 256 thr, 8x8 per thread as 8x4 packed f32x2.
// s_w folded into A-tile on smem store; bias folded as K-column 513.
// ============================================================================
__global__ __launch_bounds__(256) void k6_leaf(const float* __restrict__ Wl,
                                               const float* __restrict__ bl,
                                               float* __restrict__ out) {
    __shared__ __align__(16) float As[16][129];   // k-major
    __shared__ __align__(16) float Bs[16][130];   // k-major, even pad for 64-bit LDS
    __shared__ float Ssw[128];

    int m0 = blockIdx.y * 128, n0 = blockIdx.x * 128;
    int tid = threadIdx.x, ty = tid / 16, tx = tid % 16;
    int ar = tid >> 1, aq = (tid & 1) * 8;

    u64 acc[8][4];
    #pragma unroll
    for (int i = 0; i < 8; i++)
        #pragma unroll
        for (int jp = 0; jp < 4; jp++) acc[i][jp] = 0ull;

    for (int l = 0; l < LEAVES; l++) {
        __syncthreads();   // previous leaf fully done with Ssw/As/Bs
        if (tid < 128) Ssw[tid] = g_swt[l * BATCH + m0 + tid];
        __syncthreads();
        float s_a = Ssw[ar];
        int r = l * 256 + n0 + ar;    // W_leaf row for this thread's B loads

        for (int kt = 0; kt < 33; kt++) {
            int kk = kt * 16;
            float4 v0 = *(const float4*)(g_h + (m0 + ar) * HS + kk + aq);
            float4 v1 = *(const float4*)(g_h + (m0 + ar) * HS + kk + aq + 4);
            float bv[8];
            #pragma unroll
            for (int q = 0; q < 8; q++) {
                int d = kk + aq + q;
                float v = 0.0f;
                if (d < D1)       v = Wl[r * D1 + d];
                else if (d == D1) v = bl[r];
                bv[q] = v;
            }
            __syncthreads();   // previous k-tile compute done
            As[aq + 0][ar] = v0.x * s_a; As[aq + 1][ar] = v0.y * s_a;
            As[aq + 2][ar] = v0.z * s_a; As[aq + 3][ar] = v0.w * s_a;
            As[aq + 4][ar] = v1.x * s_a; As[aq + 5][ar] = v1.y * s_a;
            As[aq + 6][ar] = v1.z * s_a; As[aq + 7][ar] = v1.w * s_a;
            #pragma unroll
            for (int q = 0; q < 8; q++) Bs[aq + q][ar] = bv[q];
            __syncthreads();

            #pragma unroll
            for (int k = 0; k < 16; k++) {
                u64 a2[8];
                #pragma unroll
                for (int i = 0; i < 8; i++) a2[i] = pk2(As[k][ty + 16 * i]);
                u64 b2[4];
                #pragma unroll
                for (int jp = 0; jp < 4; jp++)
                    b2[jp] = *(const u64*)&Bs[k][tx * 2 + jp * 32];
                #pragma unroll
                for (int i = 0; i < 8; i++)
                    #pragma unroll
                    for (int jp = 0; jp < 4; jp++)
                        asm("fma.rn.f32x2 %0, %1, %2, %0;"
                            : "+l"(acc[i][jp]) : "l"(a2[i]), "l"(b2[jp]));
            }
        }
    }

    float scale = g_scale;
    #pragma unroll
    for (int i = 0; i < 8; i++) {
        int b = m0 + ty + 16 * i;
        #pragma unroll
        for (int jp = 0; jp < 4; jp++) {
            float lo, hi;
            asm("mov.b64 {%0,%1}, %2;" : "=f"(lo), "=f"(hi) : "l"(acc[i][jp]));
            int c = n0 + tx * 2 + jp * 32;
            out[b * DOUT + c]     = scale * lo;
            out[b * DOUT + c + 1] = scale * hi;
        }
    }
}

// ============================================================================
extern "C" void kernel_launch(void* const* d_in, const int* in_sizes, int n_in,
                              void* d_out, int out_size) {
    const float* x      = (const float*)d_in[0];
    const float* W_pre  = (const float*)d_in[1];
    const float* b_pre  = (const float*)d_in[2];
    const float* rw     = (const float*)d_in[3];
    const float* W_leaf = (const float*)d_in[4];
    const float* b_leaf = (const float*)d_in[5];
    const int*   ridx   = (const int*)d_in[6];
    const int*   rside  = (const int*)d_in[7];
    float* out = (float*)d_out;

    k0_init<<<32, 256>>>(rw);
    k1_pre<<<dim3(5, 64), 256>>>(x, W_pre, b_pre);
    k2_invh<<<1024, 256>>>();
    k3_right<<<dim3(1, 64), 256>>>(rw);
    k4_route<<<1024, 256>>>(ridx, rside);
    k5_scale<<<1, 256>>>();
    k6_leaf<<<dim3(2, 64), 256>>>(W_leaf, b_leaf, out);
}

// round 3
// speedup vs baseline: 2.9791x; 2.9791x over previous
#include <cuda_runtime.h>
#include <math.h>

// ---------------------------------------------------------------------------
// DTree forward. Round 3: leaf contraction via warp-level mma.sync tf32
// (sm_103 base target: tcgen05 is rejected by this harness's ptxas).
// out[b,o] = scale * sum_l s_w[b,l]*(h[b,:].W_leaf[l*256+o,:] + b_leaf[l*256+o])
// Single GEMM, K = 128 leaves x 544; s_w folded into A fragments in registers;
// B pre-permuted into mma fragment order (k_prep) -> linear cp.async.
// ---------------------------------------------------------------------------

#define BATCH   8192
#define DIN     512
#define D1      513
#define HS      544
#define KPAD    544
#define NKT     17
#define NODES   127
#define LEAVES  128
#define DOUT    256
#define ITERS   (NKT * LEAVES)   // 2176

typedef unsigned long long u64;
typedef unsigned int u32;

// -------------------- scratch (device globals; no allocation) --------------
__device__ __align__(16) float g_h[BATCH * HS];            // 17.8 MB
__device__ __align__(16) float g_Bp[2 * LEAVES * NKT * 4096]; // 71.3 MB fragment-ordered B
__device__ float g_swt[LEAVES * BATCH];
__device__ float g_right[BATCH * 128];
__device__ float g_invh[BATCH];
__device__ float g_invw[NODES];
__device__ float g_entpart[1024];
__device__ float g_scale;

// -------------------- helpers ----------------------------------------------
__device__ __forceinline__ u64 pk2(float x) {
    u64 r; asm("mov.b64 %0, {%1, %1};" : "=l"(r) : "f"(x)); return r;
}
__device__ __forceinline__ u32 rna_tf32(float x) {
    float r; asm("cvt.rna.tf32.f32 %0, %1;" : "=f"(r) : "f"(x));
    return __float_as_uint(r);
}
__device__ __forceinline__ u32 smem_u32(const void* p) {
    u32 a; asm("{ .reg .u64 t; cvta.to.shared.u64 t, %1; cvt.u32.u64 %0, t; }" : "=r"(a) : "l"(p));
    return a;
}
__device__ __forceinline__ void mma_tf32(float* c, u32 a0, u32 a1, u32 a2, u32 a3,
                                         u32 b0, u32 b1) {
    asm volatile("mma.sync.aligned.m16n8k8.row.col.f32.tf32.tf32.f32 "
                 "{%0,%1,%2,%3}, {%4,%5,%6,%7}, {%8,%9}, {%0,%1,%2,%3};"
                 : "+f"(c[0]), "+f"(c[1]), "+f"(c[2]), "+f"(c[3])
                 : "r"(a0), "r"(a1), "r"(a2), "r"(a3), "r"(b0), "r"(b1));
}

// ============================================================================
// k_prep: permute W_leaf|b_leaf into per-lane mma fragment order.
// g_Bp float2 index o: lane(32) | ks(4) | ntile(16) | kt(17) | l(128) | nh(2)
//   value pair = Wpad[l*256 + nh*128 + ntile*8 + lane/4][kt*32 + ks*8 + lane%4 (+4)]
// ============================================================================
__global__ void k_prep(const float* __restrict__ Wl, const float* __restrict__ bl) {
    u32 o = blockIdx.x * 256 + threadIdx.x;   // < 8,912,896
    u32 lane = o & 31; u32 t = o >> 5;
    u32 ks = t & 3; t >>= 2;
    u32 j = t & 15; t >>= 4;
    u32 kt = t % 17; t /= 17;
    u32 l = t & 127; u32 nh = t >> 7;

    int row = (int)(l * 256 + nh * 128 + j * 8 + (lane >> 2));
    int d = (int)(kt * 32 + ks * 8 + (lane & 3));
    float v0 = 0.0f, v1 = 0.0f;
    if (d < D1)            v0 = Wl[(size_t)row * D1 + d];
    else if (d == D1)      v0 = bl[row];
    int d4 = d + 4;
    if (d4 < D1)           v1 = Wl[(size_t)row * D1 + d4];
    else if (d4 == D1)     v1 = bl[row];
    float2 out;
    out.x = __uint_as_float(rna_tf32(v0));
    out.y = __uint_as_float(rna_tf32(v1));
    ((float2*)g_Bp)[o] = out;
}

// ============================================================================
// k0: pad g_h bias/zero columns; right_w inverse norms
// ============================================================================
__global__ void k0_init(const float* __restrict__ right_w) {
    int gid = blockIdx.x * 256 + threadIdx.x;
    if (gid < BATCH) {
        g_h[gid * HS + 513] = 1.0f;
        #pragma unroll
        for (int c = 514; c < HS; c++) g_h[gid * HS + c] = 0.0f;
    }
    if (blockIdx.x == 0 && threadIdx.x < NODES) {
        int n = threadIdx.x;
        float s = 0.0f;
        #pragma unroll 4
        for (int d = 0; d < D1; d++) { float v = right_w[n * D1 + d]; s += v * v; }
        g_invw[n] = 1.0f / fmaxf(sqrtf(s), 1e-12f);
    }
}

// ============================================================================
// k1: h = relu(x @ W_pre^T + b_pre)  (f32x2 packed inner loop)
// ============================================================================
__global__ __launch_bounds__(256) void k1_pre(const float* __restrict__ x,
                                              const float* __restrict__ Wp,
                                              const float* __restrict__ bp) {
    __shared__ __align__(16) float As[16][129];
    __shared__ __align__(16) float Bs[16][130];
    int m0 = blockIdx.y * 128, n0 = blockIdx.x * 128;
    int tid = threadIdx.x, ty = tid / 16, tx = tid % 16;
    int ar = tid >> 1, aq = (tid & 1) * 8;

    u64 acc[8][4];
    #pragma unroll
    for (int i = 0; i < 8; i++)
        #pragma unroll
        for (int jp = 0; jp < 4; jp++) acc[i][jp] = 0ull;

    for (int kt = 0; kt < 32; kt++) {
        int kk = kt * 16;
        float4 v0 = *(const float4*)(x + (m0 + ar) * DIN + kk + aq);
        float4 v1 = *(const float4*)(x + (m0 + ar) * DIN + kk + aq + 4);
        int n = n0 + ar;
        float4 w0 = make_float4(0.f, 0.f, 0.f, 0.f), w1 = w0;
        if (n < D1) {
            w0 = *(const float4*)(Wp + n * DIN + kk + aq);
            w1 = *(const float4*)(Wp + n * DIN + kk + aq + 4);
        }
        __syncthreads();
        As[aq + 0][ar] = v0.x; As[aq + 1][ar] = v0.y; As[aq + 2][ar] = v0.z; As[aq + 3][ar] = v0.w;
        As[aq + 4][ar] = v1.x; As[aq + 5][ar] = v1.y; As[aq + 6][ar] = v1.z; As[aq + 7][ar] = v1.w;
        Bs[aq + 0][ar] = w0.x; Bs[aq + 1][ar] = w0.y; Bs[aq + 2][ar] = w0.z; Bs[aq + 3][ar] = w0.w;
        Bs[aq + 4][ar] = w1.x; Bs[aq + 5][ar] = w1.y; Bs[aq + 6][ar] = w1.z; Bs[aq + 7][ar] = w1.w;
        __syncthreads();
        #pragma unroll
        for (int k = 0; k < 16; k++) {
            u64 a2[8], b2[4];
            #pragma unroll
            for (int i = 0; i < 8; i++) a2[i] = pk2(As[k][ty + 16 * i]);
            #pragma unroll
            for (int jp = 0; jp < 4; jp++) b2[jp] = *(const u64*)&Bs[k][tx * 2 + jp * 32];
            #pragma unroll
            for (int i = 0; i < 8; i++)
                #pragma unroll
                for (int jp = 0; jp < 4; jp++)
                    asm("fma.rn.f32x2 %0, %1, %2, %0;" : "+l"(acc[i][jp]) : "l"(a2[i]), "l"(b2[jp]));
        }
    }
    #pragma unroll
    for (int i = 0; i < 8; i++) {
        int b = m0 + ty + 16 * i;
        #pragma unroll
        for (int jp = 0; jp < 4; jp++) {
            float lo, hi;
            asm("mov.b64 {%0,%1}, %2;" : "=f"(lo), "=f"(hi) : "l"(acc[i][jp]));
            int c = n0 + tx * 2 + jp * 32;
            if (c < D1)     g_h[b * HS + c]     = fmaxf(lo + bp[c], 0.0f);
            if (c + 1 < D1) g_h[b * HS + c + 1] = fmaxf(hi + bp[c + 1], 0.0f);
        }
    }
}

// ============================================================================
// k2: per-row inverse L2 norm of h
// ============================================================================
__global__ void k2_invh() {
    int w = threadIdx.x / 32, lane = threadIdx.x % 32;
    int b = blockIdx.x * 8 + w;
    const float* row = g_h + b * HS;
    float s = 0.0f;
    for (int d = lane; d < D1; d += 32) { float v = row[d]; s += v * v; }
    #pragma unroll
    for (int o = 16; o > 0; o >>= 1) s += __shfl_xor_sync(0xffffffffu, s, o);
    if (lane == 0) g_invh[b] = 1.0f / fmaxf(sqrtf(s), 1e-12f);
}

// ============================================================================
// k3: right[b,n] = invh[b]*invw[n]*(h . right_w)
// ============================================================================
__global__ __launch_bounds__(256) void k3_right(const float* __restrict__ rw) {
    __shared__ __align__(16) float As[16][129];
    __shared__ __align__(16) float Bs[16][129];
    int m0 = blockIdx.y * 128;
    int tid = threadIdx.x, ty = tid / 16, tx = tid % 16;
    int ar = tid >> 1, aq = (tid & 1) * 8;

    float acc[8][8];
    #pragma unroll
    for (int i = 0; i < 8; i++)
        #pragma unroll
        for (int j = 0; j < 8; j++) acc[i][j] = 0.0f;

    for (int kt = 0; kt < 33; kt++) {
        int kk = kt * 16;
        float4 v0 = *(const float4*)(g_h + (m0 + ar) * HS + kk + aq);
        float4 v1 = *(const float4*)(g_h + (m0 + ar) * HS + kk + aq + 4);
        int n = ar;
        float bv[8];
        #pragma unroll
        for (int q = 0; q < 8; q++) {
            int d = kk + aq + q;
            bv[q] = (n < NODES && d < D1) ? rw[n * D1 + d] : 0.0f;
        }
        __syncthreads();
        As[aq + 0][ar] = v0.x; As[aq + 1][ar] = v0.y; As[aq + 2][ar] = v0.z; As[aq + 3][ar] = v0.w;
        As[aq + 4][ar] = v1.x; As[aq + 5][ar] = v1.y; As[aq + 6][ar] = v1.z; As[aq + 7][ar] = v1.w;
        #pragma unroll
        for (int q = 0; q < 8; q++) Bs[aq + q][ar] = bv[q];
        __syncthreads();
        #pragma unroll
        for (int k = 0; k < 16; k++) {
            float a[8], b[8];
            #pragma unroll
            for (int i = 0; i < 8; i++) a[i] = As[k][ty + 16 * i];
            #pragma unroll
            for (int j = 0; j < 8; j++) b[j] = Bs[k][tx + 16 * j];
            #pragma unroll
            for (int i = 0; i < 8; i++)
                #pragma unroll
                for (int j = 0; j < 8; j++) acc[i][j] += a[i] * b[j];
        }
    }
    #pragma unroll
    for (int i = 0; i < 8; i++) {
        int b = m0 + ty + 16 * i;
        float ih = g_invh[b];
        #pragma unroll
        for (int j = 0; j < 8; j++) {
            int n = tx + 16 * j;
            if (n < NODES) g_right[b * 128 + n] = acc[i][j] * ih * g_invw[n];
        }
    }
}

// ============================================================================
// k4: routing -> s_w (transposed), entropy partials
// ============================================================================
__global__ __launch_bounds__(256) void k4_route(const int* __restrict__ ridx,
                                                const int* __restrict__ rside) {
    __shared__ int s_idx[LEAVES * 7];
    __shared__ int s_side[LEAVES * 7];
    __shared__ float s_lr[8][128];
    __shared__ float s_ll[8][128];
    __shared__ float s_ent[8];

    int tid = threadIdx.x;
    for (int t = tid; t < LEAVES * 7; t += 256) { s_idx[t] = ridx[t]; s_side[t] = rside[t]; }
    __syncthreads();

    int w = tid / 32, lane = tid % 32;
    int b = blockIdx.x * 8 + w;

    for (int n = lane; n < NODES; n += 32) {
        float r = g_right[b * 128 + n];
        float rd = 0.5f * (1.0f - r);
        float ld = 0.5f * (1.0f + r);
        s_lr[w][n] = logf(fminf(fmaxf(rd, 0.01f), 0.99f));
        s_ll[w][n] = logf(fminf(fmaxf(ld, 0.01f), 0.99f));
    }
    __syncwarp();

    float ent = 0.0f;
    for (int li = lane; li < LEAVES; li += 32) {
        float lp = 0.0f;
        #pragma unroll
        for (int j = 0; j < 7; j++) {
            int node = s_idx[li * 7 + j];
            int side = s_side[li * 7 + j];
            lp += side ? s_ll[w][node] : s_lr[w][node];
        }
        float s = expf(lp);
        g_swt[li * BATCH + b] = s;
        ent -= s * lp;
    }
    #pragma unroll
    for (int o = 16; o > 0; o >>= 1) ent += __shfl_xor_sync(0xffffffffu, ent, o);
    if (lane == 0) s_ent[w] = ent;
    __syncthreads();
    if (tid == 0) {
        float t = 0.0f;
        #pragma unroll
        for (int i = 0; i < 8; i++) t += s_ent[i];
        g_entpart[blockIdx.x] = t;
    }
}

// ============================================================================
// k5: deterministic entropy reduction -> scale scalar
// ============================================================================
__global__ void k5_scale() {
    __shared__ float sm[256];
    float s = 0.0f;
    for (int i = threadIdx.x; i < 1024; i += 256) s += g_entpart[i];
    sm[threadIdx.x] = s;
    __syncthreads();
    for (int st = 128; st > 0; st >>= 1) {
        if (threadIdx.x < st) sm[threadIdx.x] += sm[threadIdx.x + st];
        __syncthreads();
    }
    if (threadIdx.x == 0) {
        float max_ent = (128.0f / 6.0f) * logf(6.0f);
        g_scale = 1.0f + (sm[0] / (float)BATCH) / max_ent;
    }
}

// ============================================================================
// k6_mma: mma.sync tf32 leaf contraction.
// grid (2 n-halves, 64 m-tiles), 256 thr = 8 warps, warp tile 32m x 64n.
// A built in registers per (kt, leaf); B cp.async'd in fragment order.
// SMEM: 4 x 16KB B ring.
// ============================================================================
#define SMEMSZ 65536

__global__ __launch_bounds__(256, 1) void k6_mma(float* __restrict__ out) {
    extern __shared__ __align__(128) char smem[];
    u32 sb = smem_u32(smem);
    int tid = threadIdx.x, wid = tid >> 5, lane = tid & 31;
    int nh = blockIdx.x;
    int m0 = blockIdx.y * 128;
    int mtb = (wid & 3) * 32;          // warp's row base within tile
    int ngrp = wid >> 2;               // 0/1 -> cols ngrp*64 .. +63

    u64 gBp;
    { const float* p = g_Bp; asm("cvta.to.global.u64 %0, %1;" : "=l"(gBp) : "l"(p)); }

    // cp.async prefetch of B tile 'jt' into ring slot jt&3 (16KB linear copy)
    auto prefetch_B = [&](int jt) {
        if (jt < ITERS) {
            int l = jt & 127, kt = jt >> 7;
            u64 src = gBp + ((u64)((nh * 128 + l) * 17 + kt)) * 16384ull + (u32)(tid * 16);
            u32 dst = sb + (u32)(jt & 3) * 16384u + (u32)(tid * 16);
            #pragma unroll
            for (int t = 0; t < 4; t++)
                asm volatile("cp.async.cg.shared.global [%0], [%1], 16;"
                             :: "r"(dst + t * 4096u), "l"(src + t * 4096u));
        }
        asm volatile("cp.async.commit_group;");
    };

    prefetch_B(0); prefetch_B(1); prefetch_B(2);

    float acc[2][8][4];
    #pragma unroll
    for (int mt = 0; mt < 2; mt++)
        #pragma unroll
        for (int nt = 0; nt < 8; nt++)
            #pragma unroll
            for (int q = 0; q < 4; q++) acc[mt][nt][q] = 0.0f;

    int r0 = m0 + mtb + (lane >> 2);                 // thread's base row (global)
    const float* swb = g_swt;

    int it = 0;
    #pragma unroll 1
    for (int kt = 0; kt < NKT; kt++) {
        // load this thread's h values: 4 rows (r0 + 8*rr), 8 cols (kt*32 + lane%4 + 4j)
        float hv[4][8];
        {
            const float* hp = g_h + (size_t)r0 * HS + kt * 32 + (lane & 3);
            #pragma unroll
            for (int rr = 0; rr < 4; rr++)
                #pragma unroll
                for (int j = 0; j < 8; j++)
                    hv[rr][j] = __ldg(hp + (size_t)rr * 8 * HS + j * 4);
        }

        #pragma unroll 1
        for (int l = 0; l < LEAVES; l++) {
            // s_w for this thread's 4 rows
            float sw[4];
            #pragma unroll
            for (int rr = 0; rr < 4; rr++)
                sw[rr] = __ldg(swb + l * BATCH + r0 + rr * 8);

            asm volatile("cp.async.wait_group 2;");
            __syncthreads();               // B tile (it&3) visible; prev mma done
            prefetch_B(it + 3);            // safe: slot (it-1)&3 fully consumed

            u32 Bbase = sb + (u32)(it & 3) * 16384u;
            #pragma unroll
            for (int ks = 0; ks < 4; ks++) {
                // A fragments for the 2 m-tiles (rna tf32, s_w folded)
                u32 a00 = rna_tf32(hv[0][2 * ks] * sw[0]);
                u32 a01 = rna_tf32(hv[1][2 * ks] * sw[1]);
                u32 a02 = rna_tf32(hv[0][2 * ks + 1] * sw[0]);
                u32 a03 = rna_tf32(hv[1][2 * ks + 1] * sw[1]);
                u32 a10 = rna_tf32(hv[2][2 * ks] * sw[2]);
                u32 a11 = rna_tf32(hv[3][2 * ks] * sw[3]);
                u32 a12 = rna_tf32(hv[2][2 * ks + 1] * sw[2]);
                u32 a13 = rna_tf32(hv[3][2 * ks + 1] * sw[3]);
                #pragma unroll
                for (int nt = 0; nt < 8; nt++) {
                    u32 b0, b1;
                    u32 addr = Bbase + (u32)((((ngrp * 8 + nt) * 4 + ks) * 32 + lane) * 8);
                    asm volatile("ld.shared.v2.b32 {%0,%1}, [%2];"
                                 : "=r"(b0), "=r"(b1) : "r"(addr));
                    mma_tf32(acc[0][nt], a00, a01, a02, a03, b0, b1);
                    mma_tf32(acc[1][nt], a10, a11, a12, a13, b0, b1);
                }
            }
            it++;
        }
    }

    // epilogue: scale and store (float2 per fragment half)
    float sc = g_scale;
    int n0 = nh * 128 + ngrp * 64;
    #pragma unroll
    for (int mt = 0; mt < 2; mt++) {
        #pragma unroll
        for (int half = 0; half < 2; half++) {
            int row = m0 + mtb + mt * 16 + (lane >> 2) + half * 8;
            float* op = out + (size_t)row * DOUT + n0 + (lane & 3) * 2;
            #pragma unroll
            for (int nt = 0; nt < 8; nt++) {
                float2 v;
                v.x = acc[mt][nt][half * 2] * sc;
                v.y = acc[mt][nt][half * 2 + 1] * sc;
                *(float2*)(op + nt * 8) = v;
            }
        }
    }
}

// ============================================================================
extern "C" void kernel_launch(void* const* d_in, const int* in_sizes, int n_in,
                              void* d_out, int out_size) {
    const float* x      = (const float*)d_in[0];
    const float* W_pre  = (const float*)d_in[1];
    const float* b_pre  = (const float*)d_in[2];
    const float* rw     = (const float*)d_in[3];
    const float* W_leaf = (const float*)d_in[4];
    const float* b_leaf = (const float*)d_in[5];
    const int*   ridx   = (const int*)d_in[6];
    const int*   rside  = (const int*)d_in[7];
    float* out = (float*)d_out;

    cudaFuncSetAttribute(k6_mma, cudaFuncAttributeMaxDynamicSharedMemorySize, SMEMSZ);

    k_prep<<<34816, 256>>>(W_leaf, b_leaf);
    k0_init<<<32, 256>>>(rw);
    k1_pre<<<dim3(5, 64), 256>>>(x, W_pre, b_pre);
    k2_invh<<<1024, 256>>>();
    k3_right<<<dim3(1, 64), 256>>>(rw);
    k4_route<<<1024, 256>>>(ridx, rside);
    k5_scale<<<1, 256>>>();
    k6_mma<<<dim3(2, 64), 256, SMEMSZ>>>(out);
}

// round 4
// speedup vs baseline: 6.7892x; 2.2790x over previous
#include <cuda_runtime.h>
#include <math.h>

// ---------------------------------------------------------------------------
// DTree forward. Round 4: leaf contraction via mma.sync.m16n8k16.f16
// (fp16 significand = 11 bits = tf32 precision, but 2x K per instruction).
// out[b,o] = scale * sum_l s_w[b,l]*(h[b,:].W_leaf[l*256+o,:] + b_leaf[l*256+o])
// Single GEMM, K = 128 leaves x 544; s_w folded into A fragments in registers;
// B pre-permuted into per-lane fp16 fragment order (k_prep) -> linear cp.async.
// ---------------------------------------------------------------------------

#define BATCH   8192
#define DIN     512
#define D1      513
#define HS      544
#define NKT     17
#define NODES   127
#define LEAVES  128
#define DOUT    256
#define ITERS   (NKT * LEAVES)   // 2176

typedef unsigned long long u64;
typedef unsigned int u32;

// -------------------- scratch (device globals; no allocation) --------------
__device__ __align__(16) float g_h[BATCH * HS];              // 17.8 MB
__device__ __align__(16) u32 g_Bp[2 * LEAVES * NKT * 2048];  // 35.7 MB half2 fragments
__device__ float g_swt[LEAVES * BATCH];
__device__ float g_right[BATCH * 128];
__device__ float g_invh[BATCH];
__device__ float g_invw[NODES];
__device__ float g_entpart[1024];
__device__ float g_scale;

// -------------------- helpers ----------------------------------------------
__device__ __forceinline__ u64 pk2(float x) {
    u64 r; asm("mov.b64 %0, {%1, %1};" : "=l"(r) : "f"(x)); return r;
}
__device__ __forceinline__ u32 h2(float lo, float hi) {
    u32 r; asm("cvt.rn.f16x2.f32 %0, %1, %2;" : "=r"(r) : "f"(hi), "f"(lo)); return r;
}
__device__ __forceinline__ u32 smem_u32(const void* p) {
    u32 a; asm("{ .reg .u64 t; cvta.to.shared.u64 t, %1; cvt.u32.u64 %0, t; }" : "=r"(a) : "l"(p));
    return a;
}
__device__ __forceinline__ void mma_f16(float* c, u32 a0, u32 a1, u32 a2, u32 a3,
                                        u32 b0, u32 b1) {
    asm volatile("mma.sync.aligned.m16n8k16.row.col.f32.f16.f16.f32 "
                 "{%0,%1,%2,%3}, {%4,%5,%6,%7}, {%8,%9}, {%0,%1,%2,%3};"
                 : "+f"(c[0]), "+f"(c[1]), "+f"(c[2]), "+f"(c[3])
                 : "r"(a0), "r"(a1), "r"(a2), "r"(a3), "r"(b0), "r"(b1));
}

// ============================================================================
// k_prep: permute W_leaf|b_leaf into fp16 per-lane mma fragment order.
// u32 index o bits: reg4(2) | lane(5) | ks(1) | ntp(3) | tile = ((nh*128+l)*17+kt)
//  nt = ntp*2 + (reg4>>1); reg = reg4&1
//  row = l*256 + nh*128 + nt*8 + lane/4
//  d   = kt*32 + ks*16 + (lane%4)*2 + reg*8 ; value = half2(Wpad[row][d], [d+1])
// ============================================================================
__global__ void k_prep(const float* __restrict__ Wl, const float* __restrict__ bl) {
    u32 o = blockIdx.x * 256 + threadIdx.x;   // < 8,912,896
    u32 reg4 = o & 3;
    u32 lane = (o >> 2) & 31;
    u32 ks   = (o >> 7) & 1;
    u32 ntp  = (o >> 8) & 7;
    u32 t    = o >> 11;
    u32 kt = t % 17; t /= 17;
    u32 l = t & 127; u32 nh = t >> 7;
    u32 nt = ntp * 2 + (reg4 >> 1);
    u32 reg = reg4 & 1;

    int row = (int)(l * 256 + nh * 128 + nt * 8 + (lane >> 2));
    int d = (int)(kt * 32 + ks * 16 + (lane & 3) * 2 + reg * 8);
    float v0 = 0.0f, v1 = 0.0f;
    if (d < D1)            v0 = Wl[(size_t)row * D1 + d];
    else if (d == D1)      v0 = bl[row];
    if (d + 1 < D1)        v1 = Wl[(size_t)row * D1 + d + 1];
    else if (d + 1 == D1)  v1 = bl[row];
    g_Bp[o] = h2(v0, v1);
}

// ============================================================================
// k0: pad g_h bias/zero columns; right_w inverse norms
// ============================================================================
__global__ void k0_init(const float* __restrict__ right_w) {
    int gid = blockIdx.x * 256 + threadIdx.x;
    if (gid < BATCH) {
        g_h[gid * HS + 513] = 1.0f;
        #pragma unroll
        for (int c = 514; c < HS; c++) g_h[gid * HS + c] = 0.0f;
    }
    if (blockIdx.x == 0 && threadIdx.x < NODES) {
        int n = threadIdx.x;
        float s = 0.0f;
        #pragma unroll 4
        for (int d = 0; d < D1; d++) { float v = right_w[n * D1 + d]; s += v * v; }
        g_invw[n] = 1.0f / fmaxf(sqrtf(s), 1e-12f);
    }
}

// ============================================================================
// k1: h = relu(x @ W_pre^T + b_pre)  (f32x2 packed inner loop)
// ============================================================================
__global__ __launch_bounds__(256) void k1_pre(const float* __restrict__ x,
                                              const float* __restrict__ Wp,
                                              const float* __restrict__ bp) {
    __shared__ __align__(16) float As[16][129];
    __shared__ __align__(16) float Bs[16][130];
    int m0 = blockIdx.y * 128, n0 = blockIdx.x * 128;
    int tid = threadIdx.x, ty = tid / 16, tx = tid % 16;
    int ar = tid >> 1, aq = (tid & 1) * 8;

    u64 acc[8][4];
    #pragma unroll
    for (int i = 0; i < 8; i++)
        #pragma unroll
        for (int jp = 0; jp < 4; jp++) acc[i][jp] = 0ull;

    for (int kt = 0; kt < 32; kt++) {
        int kk = kt * 16;
        float4 v0 = *(const float4*)(x + (m0 + ar) * DIN + kk + aq);
        float4 v1 = *(const float4*)(x + (m0 + ar) * DIN + kk + aq + 4);
        int n = n0 + ar;
        float4 w0 = make_float4(0.f, 0.f, 0.f, 0.f), w1 = w0;
        if (n < D1) {
            w0 = *(const float4*)(Wp + n * DIN + kk + aq);
            w1 = *(const float4*)(Wp + n * DIN + kk + aq + 4);
        }
        __syncthreads();
        As[aq + 0][ar] = v0.x; As[aq + 1][ar] = v0.y; As[aq + 2][ar] = v0.z; As[aq + 3][ar] = v0.w;
        As[aq + 4][ar] = v1.x; As[aq + 5][ar] = v1.y; As[aq + 6][ar] = v1.z; As[aq + 7][ar] = v1.w;
        Bs[aq + 0][ar] = w0.x; Bs[aq + 1][ar] = w0.y; Bs[aq + 2][ar] = w0.z; Bs[aq + 3][ar] = w0.w;
        Bs[aq + 4][ar] = w1.x; Bs[aq + 5][ar] = w1.y; Bs[aq + 6][ar] = w1.z; Bs[aq + 7][ar] = w1.w;
        __syncthreads();
        #pragma unroll
        for (int k = 0; k < 16; k++) {
            u64 a2[8], b2[4];
            #pragma unroll
            for (int i = 0; i < 8; i++) a2[i] = pk2(As[k][ty + 16 * i]);
            #pragma unroll
            for (int jp = 0; jp < 4; jp++) b2[jp] = *(const u64*)&Bs[k][tx * 2 + jp * 32];
            #pragma unroll
            for (int i = 0; i < 8; i++)
                #pragma unroll
                for (int jp = 0; jp < 4; jp++)
                    asm("fma.rn.f32x2 %0, %1, %2, %0;" : "+l"(acc[i][jp]) : "l"(a2[i]), "l"(b2[jp]));
        }
    }
    #pragma unroll
    for (int i = 0; i < 8; i++) {
        int b = m0 + ty + 16 * i;
        #pragma unroll
        for (int jp = 0; jp < 4; jp++) {
            float lo, hi;
            asm("mov.b64 {%0,%1}, %2;" : "=f"(lo), "=f"(hi) : "l"(acc[i][jp]));
            int c = n0 + tx * 2 + jp * 32;
            if (c < D1)     g_h[b * HS + c]     = fmaxf(lo + bp[c], 0.0f);
            if (c + 1 < D1) g_h[b * HS + c + 1] = fmaxf(hi + bp[c + 1], 0.0f);
        }
    }
}

// ============================================================================
// k2: per-row inverse L2 norm of h
// ============================================================================
__global__ void k2_invh() {
    int w = threadIdx.x / 32, lane = threadIdx.x % 32;
    int b = blockIdx.x * 8 + w;
    const float* row = g_h + b * HS;
    float s = 0.0f;
    for (int d = lane; d < D1; d += 32) { float v = row[d]; s += v * v; }
    #pragma unroll
    for (int o = 16; o > 0; o >>= 1) s += __shfl_xor_sync(0xffffffffu, s, o);
    if (lane == 0) g_invh[b] = 1.0f / fmaxf(sqrtf(s), 1e-12f);
}

// ============================================================================
// k3: right[b,n] = invh[b]*invw[n]*(h . right_w)
// ============================================================================
__global__ __launch_bounds__(256) void k3_right(const float* __restrict__ rw) {
    __shared__ __align__(16) float As[16][129];
    __shared__ __align__(16) float Bs[16][129];
    int m0 = blockIdx.y * 128;
    int tid = threadIdx.x, ty = tid / 16, tx = tid % 16;
    int ar = tid >> 1, aq = (tid & 1) * 8;

    float acc[8][8];
    #pragma unroll
    for (int i = 0; i < 8; i++)
        #pragma unroll
        for (int j = 0; j < 8; j++) acc[i][j] = 0.0f;

    for (int kt = 0; kt < 33; kt++) {
        int kk = kt * 16;
        float4 v0 = *(const float4*)(g_h + (m0 + ar) * HS + kk + aq);
        float4 v1 = *(const float4*)(g_h + (m0 + ar) * HS + kk + aq + 4);
        int n = ar;
        float bv[8];
        #pragma unroll
        for (int q = 0; q < 8; q++) {
            int d = kk + aq + q;
            bv[q] = (n < NODES && d < D1) ? rw[n * D1 + d] : 0.0f;
        }
        __syncthreads();
        As[aq + 0][ar] = v0.x; As[aq + 1][ar] = v0.y; As[aq + 2][ar] = v0.z; As[aq + 3][ar] = v0.w;
        As[aq + 4][ar] = v1.x; As[aq + 5][ar] = v1.y; As[aq + 6][ar] = v1.z; As[aq + 7][ar] = v1.w;
        #pragma unroll
        for (int q = 0; q < 8; q++) Bs[aq + q][ar] = bv[q];
        __syncthreads();
        #pragma unroll
        for (int k = 0; k < 16; k++) {
            float a[8], b[8];
            #pragma unroll
            for (int i = 0; i < 8; i++) a[i] = As[k][ty + 16 * i];
            #pragma unroll
            for (int j = 0; j < 8; j++) b[j] = Bs[k][tx + 16 * j];
            #pragma unroll
            for (int i = 0; i < 8; i++)
                #pragma unroll
                for (int j = 0; j < 8; j++) acc[i][j] += a[i] * b[j];
        }
    }
    #pragma unroll
    for (int i = 0; i < 8; i++) {
        int b = m0 + ty + 16 * i;
        float ih = g_invh[b];
        #pragma unroll
        for (int j = 0; j < 8; j++) {
            int n = tx + 16 * j;
            if (n < NODES) g_right[b * 128 + n] = acc[i][j] * ih * g_invw[n];
        }
    }
}

// ============================================================================
// k4: routing -> s_w (transposed), entropy partials
// ============================================================================
__global__ __launch_bounds__(256) void k4_route(const int* __restrict__ ridx,
                                                const int* __restrict__ rside) {
    __shared__ int s_idx[LEAVES * 7];
    __shared__ int s_side[LEAVES * 7];
    __shared__ float s_lr[8][128];
    __shared__ float s_ll[8][128];
    __shared__ float s_ent[8];

    int tid = threadIdx.x;
    for (int t = tid; t < LEAVES * 7; t += 256) { s_idx[t] = ridx[t]; s_side[t] = rside[t]; }
    __syncthreads();

    int w = tid / 32, lane = tid % 32;
    int b = blockIdx.x * 8 + w;

    for (int n = lane; n < NODES; n += 32) {
        float r = g_right[b * 128 + n];
        float rd = 0.5f * (1.0f - r);
        float ld = 0.5f * (1.0f + r);
        s_lr[w][n] = logf(fminf(fmaxf(rd, 0.01f), 0.99f));
        s_ll[w][n] = logf(fminf(fmaxf(ld, 0.01f), 0.99f));
    }
    __syncwarp();

    float ent = 0.0f;
    for (int li = lane; li < LEAVES; li += 32) {
        float lp = 0.0f;
        #pragma unroll
        for (int j = 0; j < 7; j++) {
            int node = s_idx[li * 7 + j];
            int side = s_side[li * 7 + j];
            lp += side ? s_ll[w][node] : s_lr[w][node];
        }
        float s = expf(lp);
        g_swt[li * BATCH + b] = s;
        ent -= s * lp;
    }
    #pragma unroll
    for (int o = 16; o > 0; o >>= 1) ent += __shfl_xor_sync(0xffffffffu, ent, o);
    if (lane == 0) s_ent[w] = ent;
    __syncthreads();
    if (tid == 0) {
        float t = 0.0f;
        #pragma unroll
        for (int i = 0; i < 8; i++) t += s_ent[i];
        g_entpart[blockIdx.x] = t;
    }
}

// ============================================================================
// k5: deterministic entropy reduction -> scale scalar
// ============================================================================
__global__ void k5_scale() {
    __shared__ float sm[256];
    float s = 0.0f;
    for (int i = threadIdx.x; i < 1024; i += 256) s += g_entpart[i];
    sm[threadIdx.x] = s;
    __syncthreads();
    for (int st = 128; st > 0; st >>= 1) {
        if (threadIdx.x < st) sm[threadIdx.x] += sm[threadIdx.x + st];
        __syncthreads();
    }
    if (threadIdx.x == 0) {
        float max_ent = (128.0f / 6.0f) * logf(6.0f);
        g_scale = 1.0f + (sm[0] / (float)BATCH) / max_ent;
    }
}

// ============================================================================
// k6_mma: fp16 m16n8k16 leaf contraction.
// grid (2 n-halves, 64 m-tiles), 256 thr = 8 warps, warp tile 32m x 64n.
// A built in registers per (kt, leaf); B cp.async'd in fragment order (8KB/tile).
// SMEM: 4 x 8KB B ring.
// ============================================================================
#define SMEMSZ 32768

__global__ __launch_bounds__(256, 1) void k6_mma(float* __restrict__ out) {
    extern __shared__ __align__(128) char smem[];
    u32 sb = smem_u32(smem);
    int tid = threadIdx.x, wid = tid >> 5, lane = tid & 31;
    int nh = blockIdx.x;
    int m0 = blockIdx.y * 128;
    int mtb = (wid & 3) * 32;          // warp's row base within tile
    int ngrp = wid >> 2;               // 0/1 -> cols ngrp*64 .. +63

    u64 gBp;
    { const u32* p = g_Bp; asm("cvta.to.global.u64 %0, %1;" : "=l"(gBp) : "l"(p)); }

    // cp.async prefetch of B tile 'jt' into ring slot jt&3 (8KB linear copy)
    auto prefetch_B = [&](int jt) {
        if (jt < ITERS) {
            int l = jt & 127, kt = jt >> 7;
            u64 src = gBp + ((u64)((nh * 128 + l) * 17 + kt)) * 8192ull + (u32)(tid * 16);
            u32 dst = sb + (u32)(jt & 3) * 8192u + (u32)(tid * 16);
            #pragma unroll
            for (int t = 0; t < 2; t++)
                asm volatile("cp.async.cg.shared.global [%0], [%1], 16;"
                             :: "r"(dst + t * 4096u), "l"(src + t * 4096u));
        }
        asm volatile("cp.async.commit_group;");
    };

    prefetch_B(0); prefetch_B(1); prefetch_B(2);

    float acc[2][8][4];
    #pragma unroll
    for (int mt = 0; mt < 2; mt++)
        #pragma unroll
        for (int nt = 0; nt < 8; nt++)
            #pragma unroll
            for (int q = 0; q < 4; q++) acc[mt][nt][q] = 0.0f;

    int r0 = m0 + mtb + (lane >> 2);                 // thread's base row (global)
    const float* swb = g_swt;

    int it = 0;
    #pragma unroll 1
    for (int kt = 0; kt < NKT; kt++) {
        // hv[rr][ks*4 + {0,1,2,3}] = h[r0+8rr, kt*32 + ks*16 + (lane&3)*2 + {0,1,8,9}]
        float hv[4][8];
        {
            const float* hp = g_h + (size_t)r0 * HS + kt * 32 + (lane & 3) * 2;
            #pragma unroll
            for (int rr = 0; rr < 4; rr++) {
                #pragma unroll
                for (int ks = 0; ks < 2; ks++) {
                    float2 p0 = *(const float2*)(hp + (size_t)rr * 8 * HS + ks * 16);
                    float2 p1 = *(const float2*)(hp + (size_t)rr * 8 * HS + ks * 16 + 8);
                    hv[rr][ks * 4 + 0] = p0.x; hv[rr][ks * 4 + 1] = p0.y;
                    hv[rr][ks * 4 + 2] = p1.x; hv[rr][ks * 4 + 3] = p1.y;
                }
            }
        }

        #pragma unroll 1
        for (int l = 0; l < LEAVES; l++) {
            float sw[4];
            #pragma unroll
            for (int rr = 0; rr < 4; rr++)
                sw[rr] = __ldg(swb + l * BATCH + r0 + rr * 8);

            asm volatile("cp.async.wait_group 2;");
            __syncthreads();               // B tile (it&3) visible; prev LDS done
            prefetch_B(it + 3);            // writes slot (it-1)&3, fully consumed

            u32 Bbase = sb + (u32)(it & 3) * 8192u;
            #pragma unroll
            for (int ks = 0; ks < 2; ks++) {
                // fp16 a-frags, s_w folded, for both m-tiles
                u32 A0[2], A1[2], A2[2], A3[2];
                #pragma unroll
                for (int mt = 0; mt < 2; mt++) {
                    int rl = 2 * mt, rh = 2 * mt + 1;
                    A0[mt] = h2(hv[rl][ks * 4 + 0] * sw[rl], hv[rl][ks * 4 + 1] * sw[rl]);
                    A1[mt] = h2(hv[rh][ks * 4 + 0] * sw[rh], hv[rh][ks * 4 + 1] * sw[rh]);
                    A2[mt] = h2(hv[rl][ks * 4 + 2] * sw[rl], hv[rl][ks * 4 + 3] * sw[rl]);
                    A3[mt] = h2(hv[rh][ks * 4 + 2] * sw[rh], hv[rh][ks * 4 + 3] * sw[rh]);
                }
                #pragma unroll
                for (int ntp = 0; ntp < 4; ntp++) {
                    u32 b00, b01, b10, b11;
                    u32 addr = Bbase + (u32)(((((ngrp * 4 + ntp) * 2 + ks) * 32) + lane) * 16);
                    asm volatile("ld.shared.v4.b32 {%0,%1,%2,%3}, [%4];"
                                 : "=r"(b00), "=r"(b01), "=r"(b10), "=r"(b11) : "r"(addr));
                    mma_f16(acc[0][2 * ntp],     A0[0], A1[0], A2[0], A3[0], b00, b01);
                    mma_f16(acc[1][2 * ntp],     A0[1], A1[1], A2[1], A3[1], b00, b01);
                    mma_f16(acc[0][2 * ntp + 1], A0[0], A1[0], A2[0], A3[0], b10, b11);
                    mma_f16(acc[1][2 * ntp + 1], A0[1], A1[1], A2[1], A3[1], b10, b11);
                }
            }
            it++;
        }
    }

    // epilogue: scale and store (float2 per fragment half)
    float sc = g_scale;
    int n0 = nh * 128 + ngrp * 64;
    #pragma unroll
    for (int mt = 0; mt < 2; mt++) {
        #pragma unroll
        for (int half = 0; half < 2; half++) {
            int row = m0 + mtb + mt * 16 + (lane >> 2) + half * 8;
            float* op = out + (size_t)row * DOUT + n0 + (lane & 3) * 2;
            #pragma unroll
            for (int nt = 0; nt < 8; nt++) {
                float2 v;
                v.x = acc[mt][nt][half * 2] * sc;
                v.y = acc[mt][nt][half * 2 + 1] * sc;
                *(float2*)(op + nt * 8) = v;
            }
        }
    }
}

// ============================================================================
extern "C" void kernel_launch(void* const* d_in, const int* in_sizes, int n_in,
                              void* d_out, int out_size) {
    const float* x      = (const float*)d_in[0];
    const float* W_pre  = (const float*)d_in[1];
    const float* b_pre  = (const float*)d_in[2];
    const float* rw     = (const float*)d_in[3];
    const float* W_leaf = (const float*)d_in[4];
    const float* b_leaf = (const float*)d_in[5];
    const int*   ridx   = (const int*)d_in[6];
    const int*   rside  = (const int*)d_in[7];
    float* out = (float*)d_out;

    cudaFuncSetAttribute(k6_mma, cudaFuncAttributeMaxDynamicSharedMemorySize, SMEMSZ);

    k_prep<<<34816, 256>>>(W_leaf, b_leaf);
    k0_init<<<32, 256>>>(rw);
    k1_pre<<<dim3(5, 64), 256>>>(x, W_pre, b_pre);
    k2_invh<<<1024, 256>>>();
    k3_right<<<dim3(1, 64), 256>>>(rw);
    k4_route<<<1024, 256>>>(ridx, rside);
    k5_scale<<<1, 256>>>();
    k6_mma<<<dim3(2, 64), 256, SMEMSZ>>>(out);
}

// round 5
// speedup vs baseline: 9.6820x; 1.4261x over previous
#include <cuda_runtime.h>
#include <cuda_fp16.h>
#include <math.h>

// ---------------------------------------------------------------------------
// DTree forward. Round 5: all GEMMs on mma.sync.m16n8k16.f16.
// - h stored as packed half2 (g_hh), s_w as packed (s,s) half2 (g_swh2)
// - B operands pre-permuted into per-lane fragment order -> direct LDG.128,
//   no shared memory, no barriers in the main GEMM loop.
// - k6: warp tile 64m x 32n, A-frags = HMUL2(h_frag, sw2), 1-deep reg prefetch.
// ---------------------------------------------------------------------------

#define BATCH   8192
#define DIN     512
#define D1      513
#define HP      272      // g_hh row stride in u32 (half2 pairs): 544 halves
#define NKT     17
#define NODES   127
#define LEAVES  128
#define DOUT    256
#define ITERS   (NKT * LEAVES)   // 2176

typedef unsigned long long u64;
typedef unsigned int u32;

// -------------------- scratch (device globals; no allocation) --------------
__device__ __align__(16) u32 g_hh[BATCH * HP];          // 8.9 MB packed half2 h
__device__ __align__(16) u32 g_Bp[LEAVES * NKT * 4096]; // 35.7 MB leaf B fragments
__device__ __align__(16) u32 g_Bpre[16 * 8192];         // 0.52 MB W_pre fragments
__device__ __align__(16) u32 g_Brw[NKT * 2048];         // 0.14 MB right_w fragments
__device__ u32 g_swh2[LEAVES * BATCH];                  // 4.2 MB (s,s) half2
__device__ float g_right[BATCH * 128];
__device__ float g_invh[BATCH];
__device__ float g_invw[NODES];
__device__ float g_entpart[1024];
__device__ float g_scale;

// -------------------- helpers ----------------------------------------------
__device__ __forceinline__ u32 h2(float lo, float hi) {
    u32 r; asm("cvt.rn.f16x2.f32 %0, %1, %2;" : "=r"(r) : "f"(hi), "f"(lo)); return r;
}
__device__ __forceinline__ u32 hmul2(u32 a, u32 b) {
    u32 r; asm("mul.f16x2 %0, %1, %2;" : "=r"(r) : "r"(a), "r"(b)); return r;
}
__device__ __forceinline__ float2 h2f(u32 v) {
    __half2 h = *reinterpret_cast<__half2*>(&v);
    return __half22float2(h);
}
__device__ __forceinline__ void mma_f16(float* c, u32 a0, u32 a1, u32 a2, u32 a3,
                                        u32 b0, u32 b1) {
    asm volatile("mma.sync.aligned.m16n8k16.row.col.f32.f16.f16.f32 "
                 "{%0,%1,%2,%3}, {%4,%5,%6,%7}, {%8,%9}, {%0,%1,%2,%3};"
                 : "+f"(c[0]), "+f"(c[1]), "+f"(c[2]), "+f"(c[3])
                 : "r"(a0), "r"(a1), "r"(a2), "r"(a3), "r"(b0), "r"(b1));
}

// Fragment addressing convention (shared by preps and GEMMs), m16n8k16:
//   B frag u32 index = ((tile*NW + nw)*2 + ks)*2 + h)*128 + lane*4 + r
//   nt = h*2 + (r>>1); reg = r&1
//   n  = nw*32 + nt*8 + (lane>>2)
//   d  = kt*32 + ks*16 + (lane&3)*2 + reg*8   (value = half2(W[n][d], W[n][d+1]))

// ============================================================================
// k_prep: leaf B fragments. tile = l*17 + kt, NW = 8 (n over 256 outputs).
// row = l*256 + n; d<513 -> W_leaf, d==513 -> b_leaf, else 0.
// ============================================================================
__global__ void k_prep(const float* __restrict__ Wl, const float* __restrict__ bl) {
    u32 o = blockIdx.x * 256 + threadIdx.x;   // < 8,912,896
    u32 r = o & 3, lane = (o >> 2) & 31;
    u32 h = (o >> 7) & 1, ks = (o >> 8) & 1, nw = (o >> 9) & 7;
    u32 t = o >> 12;
    u32 kt = t % 17, l = t / 17;
    u32 nt = h * 2 + (r >> 1), reg = r & 1;
    int n = (int)(nw * 32 + nt * 8 + (lane >> 2));
    int row = (int)(l * 256 + n);
    int d = (int)(kt * 32 + ks * 16 + (lane & 3) * 2 + reg * 8);
    float v0 = 0.0f, v1 = 0.0f;
    if (d < D1)           v0 = Wl[(size_t)row * D1 + d];
    else if (d == D1)     v0 = bl[row];
    if (d + 1 < D1)       v1 = Wl[(size_t)row * D1 + d + 1];
    else if (d + 1 == D1) v1 = bl[row];
    g_Bp[o] = h2(v0, v1);
}

// ============================================================================
// k_prep1: W_pre fragments (512x512, no bias). tile = kt, NW = 16.
// ============================================================================
__global__ void k_prep1(const float* __restrict__ Wp) {
    u32 o = blockIdx.x * 256 + threadIdx.x;   // < 131072
    u32 r = o & 3, lane = (o >> 2) & 31;
    u32 h = (o >> 7) & 1, ks = (o >> 8) & 1, nw = (o >> 9) & 15;
    u32 kt = o >> 13;
    u32 nt = h * 2 + (r >> 1), reg = r & 1;
    int n = (int)(nw * 32 + nt * 8 + (lane >> 2));            // W_pre row 0..511
    int d = (int)(kt * 32 + ks * 16 + (lane & 3) * 2 + reg * 8);
    g_Bpre[o] = h2(Wp[(size_t)n * DIN + d], Wp[(size_t)n * DIN + d + 1]);
}

// ============================================================================
// k_prep3: right_w fragments (127x513 padded to 128x544). tile = kt, NW = 4.
// ============================================================================
__global__ void k_prep3(const float* __restrict__ rw) {
    u32 o = blockIdx.x * 256 + threadIdx.x;   // < 34816
    u32 r = o & 3, lane = (o >> 2) & 31;
    u32 h = (o >> 7) & 1, ks = (o >> 8) & 1, nw = (o >> 9) & 3;
    u32 kt = o >> 11;
    u32 nt = h * 2 + (r >> 1), reg = r & 1;
    int n = (int)(nw * 32 + nt * 8 + (lane >> 2));            // node 0..127
    int d = (int)(kt * 32 + ks * 16 + (lane & 3) * 2 + reg * 8);
    float v0 = (n < NODES && d < D1)     ? rw[(size_t)n * D1 + d]     : 0.0f;
    float v1 = (n < NODES && d + 1 < D1) ? rw[(size_t)n * D1 + d + 1] : 0.0f;
    g_Brw[o] = h2(v0, v1);
}

// ============================================================================
// k0: right_w inverse row norms
// ============================================================================
__global__ void k0_init(const float* __restrict__ right_w) {
    int n = threadIdx.x;
    if (n < NODES) {
        float s = 0.0f;
        #pragma unroll 4
        for (int d = 0; d < D1; d++) { float v = right_w[n * D1 + d]; s += v * v; }
        g_invw[n] = 1.0f / fmaxf(sqrtf(s), 1e-12f);
    }
}

// ============================================================================
// k1: h[:,0:512] = relu(x @ W_pre[0:512]^T + b_pre) -> g_hh pairs 0..255
// fp16 mma, grid (4 n-tiles, 64 m-tiles), warp tile 64m x 32n, 16 kt iters.
// ============================================================================
__global__ __launch_bounds__(256, 1) void k1_pre(const float* __restrict__ x,
                                                 const float* __restrict__ bp) {
    int tid = threadIdx.x, wid = tid >> 5, lane = tid & 31;
    int mw = wid >> 2, nwl = wid & 3;
    int m0 = blockIdx.y * 128;
    int nw = blockIdx.x * 4 + nwl;
    int rbase = m0 + mw * 64 + (lane >> 2);

    const u32* Bb = g_Bpre + (size_t)nw * 512 + lane * 4;   // + kt*8192 (+ks*256+h*128)
    const float* Xb = x + (size_t)rbase * DIN + (lane & 3) * 2;

    float acc[4][4][4];
    #pragma unroll
    for (int a = 0; a < 4; a++)
        #pragma unroll
        for (int b = 0; b < 4; b++)
            #pragma unroll
            for (int c = 0; c < 4; c++) acc[a][b][c] = 0.0f;

    uint4 bb[2][2][2];
    #pragma unroll
    for (int ks = 0; ks < 2; ks++)
        #pragma unroll
        for (int h = 0; h < 2; h++)
            bb[0][ks][h] = __ldg((const uint4*)(Bb + ks * 256 + h * 128));

    #pragma unroll 2
    for (int kt = 0; kt < 16; kt++) {
        int pb = kt & 1, nb = pb ^ 1;
        if (kt + 1 < 16) {
            const u32* t = Bb + (size_t)(kt + 1) * 8192;
            #pragma unroll
            for (int ks = 0; ks < 2; ks++)
                #pragma unroll
                for (int h = 0; h < 2; h++)
                    bb[nb][ks][h] = __ldg((const uint4*)(t + ks * 256 + h * 128));
        }
        // A fragments from x (fp32 -> half2)
        u32 av[4][2][2][2];
        #pragma unroll
        for (int mt = 0; mt < 4; mt++)
            #pragma unroll
            for (int rhl = 0; rhl < 2; rhl++)
                #pragma unroll
                for (int ks = 0; ks < 2; ks++)
                    #pragma unroll
                    for (int reg = 0; reg < 2; reg++) {
                        float2 f = *(const float2*)(Xb + (size_t)(mt * 16 + rhl * 8) * DIN
                                                    + kt * 32 + ks * 16 + reg * 8);
                        av[mt][rhl][ks][reg] = h2(f.x, f.y);
                    }
        #pragma unroll
        for (int ks = 0; ks < 2; ks++)
            #pragma unroll
            for (int h = 0; h < 2; h++) {
                uint4 B = bb[pb][ks][h];
                #pragma unroll
                for (int mt = 0; mt < 4; mt++) {
                    mma_f16(acc[mt][h * 2],     av[mt][0][ks][0], av[mt][1][ks][0],
                            av[mt][0][ks][1], av[mt][1][ks][1], B.x, B.y);
                    mma_f16(acc[mt][h * 2 + 1], av[mt][0][ks][0], av[mt][1][ks][0],
                            av[mt][0][ks][1], av[mt][1][ks][1], B.z, B.w);
                }
            }
    }

    int ncol = blockIdx.x * 128 + nwl * 32 + (lane & 3) * 2;
    #pragma unroll
    for (int mt = 0; mt < 4; mt++)
        #pragma unroll
        for (int half = 0; half < 2; half++) {
            int row = rbase + mt * 16 + half * 8;
            #pragma unroll
            for (int nt = 0; nt < 4; nt++) {
                int n = ncol + nt * 8;
                float v0 = fmaxf(acc[mt][nt][half * 2]     + __ldg(bp + n),     0.0f);
                float v1 = fmaxf(acc[mt][nt][half * 2 + 1] + __ldg(bp + n + 1), 0.0f);
                g_hh[(size_t)row * HP + (n >> 1)] = h2(v0, v1);
            }
        }
}

// ============================================================================
// k1b: h[:,512] = relu(x . W_pre[512] + b[512]); write pair 256 = (h512, 1.0)
// and zero pads 257..271. One warp per row.
// ============================================================================
__global__ void k1b(const float* __restrict__ x, const float* __restrict__ Wp,
                    const float* __restrict__ bp) {
    int w = threadIdx.x >> 5, lane = threadIdx.x & 31;
    int b = blockIdx.x * 8 + w;
    const float* xr = x + (size_t)b * DIN;
    const float* wr = Wp + (size_t)512 * DIN;
    float s = 0.0f;
    #pragma unroll 4
    for (int d = lane; d < DIN; d += 32) s += xr[d] * wr[d];
    #pragma unroll
    for (int o = 16; o > 0; o >>= 1) s += __shfl_xor_sync(0xffffffffu, s, o);
    if (lane == 0) {
        float h512 = fmaxf(s + bp[512], 0.0f);
        g_hh[(size_t)b * HP + 256] = h2(h512, 1.0f);
    } else if (lane < 16) {
        g_hh[(size_t)b * HP + 256 + lane] = 0u;
    }
}

// ============================================================================
// k2: per-row inverse L2 norm of h (513 dims) from g_hh
// ============================================================================
__global__ void k2_invh() {
    int w = threadIdx.x >> 5, lane = threadIdx.x & 31;
    int b = blockIdx.x * 8 + w;
    const u32* row = g_hh + (size_t)b * HP;
    float s = 0.0f;
    for (int i = lane; i < 256; i += 32) {
        float2 f = h2f(row[i]);
        s += f.x * f.x + f.y * f.y;
    }
    if (lane == 0) { float2 f = h2f(row[256]); s += f.x * f.x; }
    #pragma unroll
    for (int o = 16; o > 0; o >>= 1) s += __shfl_xor_sync(0xffffffffu, s, o);
    if (lane == 0) g_invh[b] = 1.0f / fmaxf(sqrtf(s), 1e-12f);
}

// ============================================================================
// k3: right[b,n] = invh[b]*invw[n]*(h . right_w[n])  -- fp16 mma, A = g_hh raw
// grid (1, 64), N=128 (127 real), 17 kt iters.
// ============================================================================
__global__ __launch_bounds__(256, 1) void k3_right() {
    int tid = threadIdx.x, wid = tid >> 5, lane = tid & 31;
    int mw = wid >> 2, nwl = wid & 3;
    int m0 = blockIdx.y * 128;
    int rbase = m0 + mw * 64 + (lane >> 2);

    const u32* Bb = g_Brw + (size_t)nwl * 512 + lane * 4;   // + kt*2048
    const u32* Hb = g_hh + (size_t)rbase * HP + (lane & 3);

    float acc[4][4][4];
    #pragma unroll
    for (int a = 0; a < 4; a++)
        #pragma unroll
        for (int b = 0; b < 4; b++)
            #pragma unroll
            for (int c = 0; c < 4; c++) acc[a][b][c] = 0.0f;

    #pragma unroll 1
    for (int kt = 0; kt < 17; kt++) {
        uint4 bb[2][2];
        #pragma unroll
        for (int ks = 0; ks < 2; ks++)
            #pragma unroll
            for (int h = 0; h < 2; h++)
                bb[ks][h] = __ldg((const uint4*)(Bb + (size_t)kt * 2048 + ks * 256 + h * 128));
        u32 hv[4][2][2][2];
        #pragma unroll
        for (int mt = 0; mt < 4; mt++)
            #pragma unroll
            for (int rhl = 0; rhl < 2; rhl++)
                #pragma unroll
                for (int ks = 0; ks < 2; ks++)
                    #pragma unroll
                    for (int reg = 0; reg < 2; reg++)
                        hv[mt][rhl][ks][reg] = __ldg(Hb + (size_t)(mt * 16 + rhl * 8) * HP
                                                     + kt * 16 + ks * 8 + reg * 4);
        #pragma unroll
        for (int ks = 0; ks < 2; ks++)
            #pragma unroll
            for (int h = 0; h < 2; h++) {
                uint4 B = bb[ks][h];
                #pragma unroll
                for (int mt = 0; mt < 4; mt++) {
                    mma_f16(acc[mt][h * 2],     hv[mt][0][ks][0], hv[mt][1][ks][0],
                            hv[mt][0][ks][1], hv[mt][1][ks][1], B.x, B.y);
                    mma_f16(acc[mt][h * 2 + 1], hv[mt][0][ks][0], hv[mt][1][ks][0],
                            hv[mt][0][ks][1], hv[mt][1][ks][1], B.z, B.w);
                }
            }
    }

    #pragma unroll
    for (int mt = 0; mt < 4; mt++)
        #pragma unroll
        for (int half = 0; half < 2; half++) {
            int row = rbase + mt * 16 + half * 8;
            float ih = g_invh[row];
            #pragma unroll
            for (int nt = 0; nt < 4; nt++) {
                int n = nwl * 32 + nt * 8 + (lane & 3) * 2;
                if (n < NODES)
                    g_right[(size_t)row * 128 + n] = acc[mt][nt][half * 2] * ih * g_invw[n];
                if (n + 1 < NODES)
                    g_right[(size_t)row * 128 + n + 1] = acc[mt][nt][half * 2 + 1] * ih * g_invw[n + 1];
            }
        }
}

// ============================================================================
// k4: routing -> g_swh2 (packed (s,s) half2, [l][b]), entropy partials
// ============================================================================
__global__ __launch_bounds__(256) void k4_route(const int* __restrict__ ridx,
                                                const int* __restrict__ rside) {
    __shared__ int s_idx[LEAVES * 7];
    __shared__ int s_side[LEAVES * 7];
    __shared__ float s_lr[8][128];
    __shared__ float s_ll[8][128];
    __shared__ float s_ent[8];

    int tid = threadIdx.x;
    for (int t = tid; t < LEAVES * 7; t += 256) { s_idx[t] = ridx[t]; s_side[t] = rside[t]; }
    __syncthreads();

    int w = tid / 32, lane = tid % 32;
    int b = blockIdx.x * 8 + w;

    for (int n = lane; n < NODES; n += 32) {
        float r = g_right[b * 128 + n];
        float rd = 0.5f * (1.0f - r);
        float ld = 0.5f * (1.0f + r);
        s_lr[w][n] = logf(fminf(fmaxf(rd, 0.01f), 0.99f));
        s_ll[w][n] = logf(fminf(fmaxf(ld, 0.01f), 0.99f));
    }
    __syncwarp();

    float ent = 0.0f;
    for (int li = lane; li < LEAVES; li += 32) {
        float lp = 0.0f;
        #pragma unroll
        for (int j = 0; j < 7; j++) {
            int node = s_idx[li * 7 + j];
            int side = s_side[li * 7 + j];
            lp += side ? s_ll[w][node] : s_lr[w][node];
        }
        float s = expf(lp);
        g_swh2[li * BATCH + b] = h2(s, s);
        ent -= s * lp;
    }
    #pragma unroll
    for (int o = 16; o > 0; o >>= 1) ent += __shfl_xor_sync(0xffffffffu, ent, o);
    if (lane == 0) s_ent[w] = ent;
    __syncthreads();
    if (tid == 0) {
        float t = 0.0f;
        #pragma unroll
        for (int i = 0; i < 8; i++) t += s_ent[i];
        g_entpart[blockIdx.x] = t;
    }
}

// ============================================================================
// k5: deterministic entropy reduction -> scale scalar
// ============================================================================
__global__ void k5_scale() {
    __shared__ float sm[256];
    float s = 0.0f;
    for (int i = threadIdx.x; i < 1024; i += 256) s += g_entpart[i];
    sm[threadIdx.x] = s;
    __syncthreads();
    for (int st = 128; st > 0; st >>= 1) {
        if (threadIdx.x < st) sm[threadIdx.x] += sm[threadIdx.x + st];
        __syncthreads();
    }
    if (threadIdx.x == 0) {
        float max_ent = (128.0f / 6.0f) * logf(6.0f);
        g_scale = 1.0f + (sm[0] / (float)BATCH) / max_ent;
    }
}

// ============================================================================
// k6: fp16 mma leaf contraction, no smem, no barriers.
// grid (2 n-halves, 64 m-tiles), 8 warps, warp tile 64m x 32n.
// A = HMUL2(h_frag, sw2); B direct LDG.128 with 1-deep register prefetch.
// ============================================================================
__global__ __launch_bounds__(256, 1) void k6_mma(float* __restrict__ out) {
    int tid = threadIdx.x, wid = tid >> 5, lane = tid & 31;
    int mw = wid >> 2, nwl = wid & 3;
    int m0 = blockIdx.y * 128;
    int nw = blockIdx.x * 4 + nwl;
    int rbase = m0 + mw * 64 + (lane >> 2);

    const u32* Bb = g_Bp + (size_t)nw * 512 + lane * 4;     // + tile*4096 (+ks*256+h*128)
    const u32* SWb = g_swh2 + rbase;                        // + l*8192 + row offsets
    const u32* Hb = g_hh + (size_t)rbase * HP + (lane & 3);

    float acc[4][4][4];
    #pragma unroll
    for (int a = 0; a < 4; a++)
        #pragma unroll
        for (int b = 0; b < 4; b++)
            #pragma unroll
            for (int c = 0; c < 4; c++) acc[a][b][c] = 0.0f;

    uint4 bb[2][2][2];       // [buf][ks][h]
    u32 sw[2][8];            // [buf][mt*2 + rhl]
    u32 hv[4][2][2][2];      // [mt][rhl][ks][reg]

    // preload it=0 (kt=0, l=0)
    #pragma unroll
    for (int ks = 0; ks < 2; ks++)
        #pragma unroll
        for (int h = 0; h < 2; h++)
            bb[0][ks][h] = __ldg((const uint4*)(Bb + ks * 256 + h * 128));
    #pragma unroll
    for (int j = 0; j < 8; j++)
        sw[0][j] = __ldg(SWb + (j >> 1) * 16 + (j & 1) * 8);

    int it = 0;
    #pragma unroll 1
    for (int kt = 0; kt < NKT; kt++) {
        #pragma unroll
        for (int mt = 0; mt < 4; mt++)
            #pragma unroll
            for (int rhl = 0; rhl < 2; rhl++)
                #pragma unroll
                for (int ks = 0; ks < 2; ks++)
                    #pragma unroll
                    for (int reg = 0; reg < 2; reg++)
                        hv[mt][rhl][ks][reg] = __ldg(Hb + (size_t)(mt * 16 + rhl * 8) * HP
                                                     + kt * 16 + ks * 8 + reg * 4);
        #pragma unroll 2
        for (int l = 0; l < LEAVES; l++) {
            int pb = l & 1, nb = pb ^ 1;
            int nit = it + 1;
            if (nit < ITERS) {
                int nl = nit & 127, nkt = nit >> 7;
                const u32* t = Bb + (size_t)(nl * 17 + nkt) * 4096;
                #pragma unroll
                for (int ks = 0; ks < 2; ks++)
                    #pragma unroll
                    for (int h = 0; h < 2; h++)
                        bb[nb][ks][h] = __ldg((const uint4*)(t + ks * 256 + h * 128));
                const u32* sp = SWb + (size_t)nl * BATCH;
                #pragma unroll
                for (int j = 0; j < 8; j++)
                    sw[nb][j] = __ldg(sp + (j >> 1) * 16 + (j & 1) * 8);
            }
            #pragma unroll
            for (int ks = 0; ks < 2; ks++) {
                u32 A0[4], A1[4], A2[4], A3[4];
                #pragma unroll
                for (int mt = 0; mt < 4; mt++) {
                    A0[mt] = hmul2(hv[mt][0][ks][0], sw[pb][mt * 2]);
                    A1[mt] = hmul2(hv[mt][1][ks][0], sw[pb][mt * 2 + 1]);
                    A2[mt] = hmul2(hv[mt][0][ks][1], sw[pb][mt * 2]);
                    A3[mt] = hmul2(hv[mt][1][ks][1], sw[pb][mt * 2 + 1]);
                }
                #pragma unroll
                for (int h = 0; h < 2; h++) {
                    uint4 B = bb[pb][ks][h];
                    #pragma unroll
                    for (int mt = 0; mt < 4; mt++) {
                        mma_f16(acc[mt][h * 2],     A0[mt], A1[mt], A2[mt], A3[mt], B.x, B.y);
                        mma_f16(acc[mt][h * 2 + 1], A0[mt], A1[mt], A2[mt], A3[mt], B.z, B.w);
                    }
                }
            }
            it++;
        }
    }

    float sc = g_scale;
    int ncol = blockIdx.x * 128 + nwl * 32 + (lane & 3) * 2;
    #pragma unroll
    for (int mt = 0; mt < 4; mt++)
        #pragma unroll
        for (int half = 0; half < 2; half++) {
            int row = rbase + mt * 16 + half * 8;
            float* op = out + (size_t)row * DOUT + ncol;
            #pragma unroll
            for (int nt = 0; nt < 4; nt++) {
                float2 v;
                v.x = acc[mt][nt][half * 2] * sc;
                v.y = acc[mt][nt][half * 2 + 1] * sc;
                *(float2*)(op + nt * 8) = v;
            }
        }
}

// ============================================================================
extern "C" void kernel_launch(void* const* d_in, const int* in_sizes, int n_in,
                              void* d_out, int out_size) {
    const float* x      = (const float*)d_in[0];
    const float* W_pre  = (const float*)d_in[1];
    const float* b_pre  = (const float*)d_in[2];
    const float* rw     = (const float*)d_in[3];
    const float* W_leaf = (const float*)d_in[4];
    const float* b_leaf = (const float*)d_in[5];
    const int*   ridx   = (const int*)d_in[6];
    const int*   rside  = (const int*)d_in[7];
    float* out = (float*)d_out;

    k_prep<<<34816, 256>>>(W_leaf, b_leaf);
    k_prep1<<<512, 256>>>(W_pre);
    k_prep3<<<136, 256>>>(rw);
    k0_init<<<1, 128>>>(rw);
    k1_pre<<<dim3(4, 64), 256>>>(x, b_pre);
    k1b<<<1024, 256>>>(x, W_pre, b_pre);
    k2_invh<<<1024, 256>>>();
    k3_right<<<dim3(1, 64), 256>>>();
    k4_route<<<1024, 256>>>(ridx, rside);
    k5_scale<<<1, 256>>>();
    k6_mma<<<dim3(2, 64), 256>>>(out);
}